// round 2
// baseline (speedup 1.0000x reference)
#include <cuda_runtime.h>

#define NB   8192      // B*N total rows
#define NPTS 4096      // nodes per batch
#define FDIM 64
#define KSEL 21        // k+1 (drop the smallest afterwards)
#define QPB  4         // queries per block in knn kernel
#define TPB  512

// ---------------- scratch (device globals; no allocation allowed) ----------
__device__ float4 g_pos4[NB];          // (x,y,z,sq)
__device__ float  g_Wh[NB * FDIM];
__device__ float  g_f1[NB];
__device__ float  g_f2[NB];
__device__ float  g_base[NB * FDIM];   // relu(pos@Wp + bp)

// order-preserving float->uint transform (handles negatives from rounding)
__device__ __forceinline__ unsigned int fkey(float f) {
    unsigned int b = __float_as_uint(f);
    return (b & 0x80000000u) ? ~b : (b | 0x80000000u);
}
__device__ __forceinline__ unsigned long long ullmin2(unsigned long long a,
                                                      unsigned long long b) {
    return a < b ? a : b;
}

// ---------------- kernel A: per-node prep ----------------------------------
__global__ void prep_kernel(const float* __restrict__ x,
                            const float* __restrict__ pos,
                            const float* __restrict__ W,
                            const float* __restrict__ a,
                            const float* __restrict__ Wp,
                            const float* __restrict__ bp) {
    int row = blockIdx.x;        // 0..NB-1
    int j   = threadIdx.x;       // 0..63
    __shared__ float xs[FDIM];
    __shared__ float red[4];

    xs[j] = x[row * FDIM + j];
    __syncthreads();

    float acc = 0.f;
#pragma unroll 16
    for (int i = 0; i < FDIM; i++)
        acc += xs[i] * W[i * FDIM + j];
    g_Wh[row * FDIM + j] = acc;

    // f1 = Wh . a[0:64], f2 = Wh . a[64:128]
    float p1 = acc * a[j];
    float p2 = acc * a[FDIM + j];
#pragma unroll
    for (int off = 16; off; off >>= 1) {
        p1 += __shfl_down_sync(0xffffffffu, p1, off);
        p2 += __shfl_down_sync(0xffffffffu, p2, off);
    }
    int lane = j & 31, wid = j >> 5;
    if (lane == 0) { red[wid] = p1; red[2 + wid] = p2; }

    // base = relu(pos @ Wp + bp)    Wp is (3, 64) row-major
    float px = pos[row * 3 + 0];
    float py = pos[row * 3 + 1];
    float pz = pos[row * 3 + 2];
    float bj = px * Wp[j] + py * Wp[FDIM + j] + pz * Wp[2 * FDIM + j] + bp[j];
    g_base[row * FDIM + j] = bj > 0.f ? bj : 0.f;

    __syncthreads();
    if (j == 0) {
        g_f1[row] = red[0] + red[1];
        g_f2[row] = red[2] + red[3];
        float sq  = px * px + py * py + pz * pz;   // same formula as reference
        g_pos4[row] = make_float4(px, py, pz, sq);
    }
}

// ---------------- kernel B: kNN(21) + attention epilogue --------------------
// One block = QPB consecutive queries (same batch). 128 threads per query.
// Dynamic smem: keys[QPB][NPTS] (uint32) = 64 KB.
__global__ void __launch_bounds__(TPB)
knn_attn_kernel(float* __restrict__ out) {
    extern __shared__ unsigned int keys[];   // [QPB * NPTS]
    __shared__ float4 s_q[QPB];
    __shared__ unsigned long long s_wmin[QPB][4];
    __shared__ unsigned long long s_winner[QPB];
    __shared__ int   s_nbr[QPB][KSEL - 1];
    __shared__ float s_attn[QPB][KSEL - 1];

    int tid = threadIdx.x;
    int sub = tid >> 7;          // which query slot (0..3)
    int t   = tid & 127;         // thread within query group
    int qbase    = blockIdx.x * QPB;   // first global row of block
    int b        = qbase >> 12;        // batch
    int browbase = b << 12;            // first row of this batch
    int row      = qbase + sub;        // this subgroup's query row

    if (tid < QPB) s_q[tid] = g_pos4[qbase + tid];
    __syncthreads();
    float4 q0 = s_q[0], q1 = s_q[1], q2 = s_q[2], q3 = s_q[3];

    // ---- distance phase: each pos4 element loaded ONCE per block ----
#pragma unroll
    for (int jj = 0; jj < 8; jj++) {
        int m = (sub * 8 + jj) * 128 + t;          // covers 0..4095 uniquely
        float4 p = g_pos4[browbase + m];
        float d0 = q0.w + p.w - 2.f * (q0.x * p.x + q0.y * p.y + q0.z * p.z);
        float d1 = q1.w + p.w - 2.f * (q1.x * p.x + q1.y * p.y + q1.z * p.z);
        float d2 = q2.w + p.w - 2.f * (q2.x * p.x + q2.y * p.y + q2.z * p.z);
        float d3 = q3.w + p.w - 2.f * (q3.x * p.x + q3.y * p.y + q3.z * p.z);
        keys[0 * NPTS + m] = fkey(d0);
        keys[1 * NPTS + m] = fkey(d1);
        keys[2 * NPTS + m] = fkey(d2);
        keys[3 * NPTS + m] = fkey(d3);
    }
    __syncthreads();

    // ---- per-thread min over own 32 candidates of this subgroup ----
    unsigned int* mykeys = keys + sub * NPTS;
    unsigned long long v = ~0ull;
#pragma unroll
    for (int jj = 0; jj < 32; jj++) {
        int m = jj * 128 + t;
        unsigned long long k64 =
            (((unsigned long long)mykeys[m]) << 12) | (unsigned int)m;
        v = ullmin2(v, k64);
    }

    int lane = tid & 31;
    int w    = (tid >> 5) & 3;   // warp within subgroup

    // ---- 21 rounds of extract-min with single-owner repair ----
    for (int r = 0; r < KSEL; r++) {
        unsigned long long vv = v;
#pragma unroll
        for (int off = 16; off; off >>= 1)
            vv = ullmin2(vv, __shfl_down_sync(0xffffffffu, vv, off));
        if (lane == 0) s_wmin[sub][w] = vv;
        __syncthreads();
        if (t == 0) {
            unsigned long long a0 = ullmin2(s_wmin[sub][0], s_wmin[sub][1]);
            unsigned long long a1 = ullmin2(s_wmin[sub][2], s_wmin[sub][3]);
            s_winner[sub] = ullmin2(a0, a1);
        }
        __syncthreads();
        unsigned long long win = s_winner[sub];
        int mwin = (int)(win & 0xFFFu);
        if (t == 0 && r > 0) s_nbr[sub][r - 1] = mwin;   // drop round-0 (global min)
        if (t == (mwin & 127)) {                         // owner repairs its chunk
            mykeys[mwin] = 0xFFFFFFFFu;
            unsigned long long nb = ~0ull;
#pragma unroll
            for (int jj = 0; jj < 32; jj++) {
                int m = jj * 128 + t;
                unsigned long long k64 =
                    (((unsigned long long)mykeys[m]) << 12) | (unsigned int)m;
                nb = ullmin2(nb, k64);
            }
            v = nb;
        }
        // no extra sync needed: only owner's private state changed
    }
    __syncthreads();

    // ---- softmax over the 20 neighbors (warp 0 of each subgroup) ----
    if (t < 32) {
        float e = -1e30f;
        if (t < KSEL - 1) {
            int m = s_nbr[sub][t];
            float val = g_f1[row] + g_f2[browbase + m];
            e = val > 0.f ? val : 0.2f * val;          // leaky relu 0.2
        }
        float mx = e;
#pragma unroll
        for (int off = 16; off; off >>= 1)
            mx = fmaxf(mx, __shfl_xor_sync(0xffffffffu, mx, off));
        float ex = (t < KSEL - 1) ? expf(e - mx) : 0.f;
        float sm = ex;
#pragma unroll
        for (int off = 16; off; off >>= 1)
            sm += __shfl_xor_sync(0xffffffffu, sm, off);
        if (t < KSEL - 1) s_attn[sub][t] = ex / sm;
    }
    __syncthreads();

    // ---- weighted Wh gather + base + elu ----
    if (t < FDIM) {
        float acc = g_base[row * FDIM + t];
#pragma unroll
        for (int i = 0; i < KSEL - 1; i++) {
            int m = s_nbr[sub][i];
            acc += s_attn[sub][i] * g_Wh[(browbase + m) * FDIM + t];
        }
        float o = acc > 0.f ? acc : expm1f(acc);       // elu(alpha=1)
        out[row * FDIM + t] = o;
    }
}

// ---------------- launch ----------------------------------------------------
extern "C" void kernel_launch(void* const* d_in, const int* in_sizes, int n_in,
                              void* d_out, int out_size) {
    (void)in_sizes; (void)n_in; (void)out_size;
    const float* x   = (const float*)d_in[0];
    const float* pos = (const float*)d_in[1];
    const float* W   = (const float*)d_in[2];
    const float* a   = (const float*)d_in[3];
    const float* Wp  = (const float*)d_in[4];
    const float* bp  = (const float*)d_in[5];
    // d_in[6] = k (always 20 for this problem; hardcoded as KSEL-1)
    float* out = (float*)d_out;

    prep_kernel<<<NB, FDIM>>>(x, pos, W, a, Wp, bp);

    cudaFuncSetAttribute(knn_attn_kernel,
                         cudaFuncAttributeMaxDynamicSharedMemorySize,
                         QPB * NPTS * (int)sizeof(unsigned int));
    knn_attn_kernel<<<NB / QPB, TPB, QPB * NPTS * sizeof(unsigned int)>>>(out);
}

// round 3
// speedup vs baseline: 1.0368x; 1.0368x over previous
#include <cuda_runtime.h>

#define NB    8192     // B*N total rows
#define NPTS  4096     // nodes per batch
#define FDIM  64
#define KSEL  21       // k+1 (drop the smallest afterwards)
#define QPB   4        // queries per block
#define TPB   512
#define CHUNK 1024     // pos4 staging chunk (float4 count)

// ---------------- scratch (device globals; no allocation allowed) ----------
__device__ float4 g_pos4[NB];          // (x,y,z,sq)
__device__ float  g_Wh[NB * FDIM];
__device__ float  g_f1[NB];
__device__ float  g_f2[NB];
__device__ float  g_base[NB * FDIM];   // relu(pos@Wp + bp)

// order-preserving float->uint transform
__device__ __forceinline__ unsigned int fkey(float f) {
    unsigned int b = __float_as_uint(f);
    return (b & 0x80000000u) ? ~b : (b | 0x80000000u);
}
__device__ __forceinline__ unsigned long long ullmin2(unsigned long long a,
                                                      unsigned long long b) {
    return a < b ? a : b;
}

// ---------------- kernel A: per-node prep ----------------------------------
__global__ void prep_kernel(const float* __restrict__ x,
                            const float* __restrict__ pos,
                            const float* __restrict__ W,
                            const float* __restrict__ a,
                            const float* __restrict__ Wp,
                            const float* __restrict__ bp) {
    int row = blockIdx.x;        // 0..NB-1
    int j   = threadIdx.x;       // 0..63
    __shared__ float xs[FDIM];
    __shared__ float red[4];

    xs[j] = x[row * FDIM + j];
    __syncthreads();

    float acc = 0.f;
#pragma unroll 16
    for (int i = 0; i < FDIM; i++)
        acc += xs[i] * W[i * FDIM + j];
    g_Wh[row * FDIM + j] = acc;

    float p1 = acc * a[j];
    float p2 = acc * a[FDIM + j];
#pragma unroll
    for (int off = 16; off; off >>= 1) {
        p1 += __shfl_down_sync(0xffffffffu, p1, off);
        p2 += __shfl_down_sync(0xffffffffu, p2, off);
    }
    int lane = j & 31, wid = j >> 5;
    if (lane == 0) { red[wid] = p1; red[2 + wid] = p2; }

    float px = pos[row * 3 + 0];
    float py = pos[row * 3 + 1];
    float pz = pos[row * 3 + 2];
    float bj = px * Wp[j] + py * Wp[FDIM + j] + pz * Wp[2 * FDIM + j] + bp[j];
    g_base[row * FDIM + j] = bj > 0.f ? bj : 0.f;

    __syncthreads();
    if (j == 0) {
        g_f1[row] = red[0] + red[1];
        g_f2[row] = red[2] + red[3];
        float sq  = px * px + py * py + pz * pz;
        g_pos4[row] = make_float4(px, py, pz, sq);
    }
}

// ---------------- kernel B: kNN(21) + attention epilogue --------------------
// Block = 4 queries. 128 threads per query. Each thread owns the 32
// candidates m ≡ t (mod 128) and keeps a register sorted top-4 + bound.
// One warp per query then 128-way-merges the sorted streams (21 rounds of
// warp shfl min). Exact fallback (named barriers) if a bound is ever hit.
__global__ void __launch_bounds__(TPB)
knn_attn_kernel(float* __restrict__ out) {
    __shared__ float4 s_chunk[CHUNK];                       // 16 KB
    __shared__ unsigned long long s_lists[QPB][128][5];     // 20 KB
    __shared__ float4 s_q[QPB];
    __shared__ int    s_nbr[QPB][KSEL - 1];
    __shared__ float  s_attn[QPB][KSEL - 1];
    __shared__ int    s_bad[QPB];
    __shared__ unsigned long long s_wmin[QPB][4];
    __shared__ unsigned long long s_winner[QPB];

    int tid = threadIdx.x;
    int sub = tid >> 7;          // query slot (0..3)
    int t   = tid & 127;         // thread within query group
    int qbase    = blockIdx.x * QPB;
    int browbase = (qbase >> 12) << 12;    // first row of this batch
    int row      = qbase + sub;

    if (tid < QPB) { s_q[tid] = g_pos4[qbase + tid]; s_bad[tid] = 0; }
    __syncthreads();
    float4 q = s_q[sub];

    // ---- phase 1: distances + register top-4 (+ bound) ----
    unsigned long long r0 = ~0ull, r1 = ~0ull, r2 = ~0ull, r3 = ~0ull, r4 = ~0ull;
#pragma unroll 1
    for (int c = 0; c < NPTS / CHUNK; c++) {
        s_chunk[tid]       = g_pos4[browbase + c * CHUNK + tid];
        s_chunk[tid + TPB] = g_pos4[browbase + c * CHUNK + tid + TPB];
        __syncthreads();
#pragma unroll
        for (int j = 0; j < CHUNK / 128; j++) {
            int mloc = t + 128 * j;
            float4 p = s_chunk[mloc];
            float d2 = q.w + p.w - 2.f * (q.x * p.x + q.y * p.y + q.z * p.z);
            int m = c * CHUNK + mloc;
            unsigned long long k64 =
                (((unsigned long long)fkey(d2)) << 13) | (unsigned int)m;
            if (k64 < r4) {
                r4 = k64;
                unsigned long long tmp;
                if (r4 < r3) { tmp = r3; r3 = r4; r4 = tmp; }
                if (r3 < r2) { tmp = r2; r2 = r3; r3 = tmp; }
                if (r2 < r1) { tmp = r1; r1 = r2; r2 = tmp; }
                if (r1 < r0) { tmp = r0; r0 = r1; r1 = tmp; }
            }
        }
        __syncthreads();
    }
    r4 |= 0x1000ull;   // mark bound element (5th smallest) with flag bit 12
    s_lists[sub][t][0] = r0;
    s_lists[sub][t][1] = r1;
    s_lists[sub][t][2] = r2;
    s_lists[sub][t][3] = r3;
    s_lists[sub][t][4] = r4;
    __syncthreads();

    // ---- phase 2: 128-way merge, one warp per query ----
    if (t < 32) {
        int l = t;    // lane
        unsigned long long h[4];
        int pos[4];
#pragma unroll
        for (int s = 0; s < 4; s++) {
            h[s] = s_lists[sub][4 * l + s][0];
            pos[s] = 1;
        }
#pragma unroll 1
        for (int r = 0; r < KSEL; r++) {
            unsigned long long cur = ullmin2(ullmin2(h[0], h[1]),
                                             ullmin2(h[2], h[3]));
#pragma unroll
            for (int off = 16; off; off >>= 1)
                cur = ullmin2(cur, __shfl_xor_sync(0xffffffffu, cur, off));
            if ((cur >> 12) & 1ull) {
                if (l == 0) s_bad[sub] = 1;      // bound selected -> fallback
            }
            int m = (int)cur & 0xFFF;
            if (l == 0 && r > 0) s_nbr[sub][r - 1] = m;
#pragma unroll
            for (int s = 0; s < 4; s++) {
                if (h[s] == cur) {
                    h[s] = (pos[s] < 5) ? s_lists[sub][4 * l + s][pos[s]] : ~0ull;
                    pos[s]++;
                }
            }
        }
    }
    __syncthreads();

    // ---- exact fallback (rare): recompute scan with removal bitmap ----
    if (s_bad[sub]) {
        unsigned int removed = 0;
        int lane = t & 31, w = t >> 5;
        // initial per-thread min (recompute distances; L2-hot)
        unsigned long long v = ~0ull;
#pragma unroll 1
        for (int i = 0; i < 32; i++) {
            int m = t + 128 * i;
            float4 p = g_pos4[browbase + m];
            float d2 = q.w + p.w - 2.f * (q.x * p.x + q.y * p.y + q.z * p.z);
            unsigned long long k64 =
                (((unsigned long long)fkey(d2)) << 13) | (unsigned int)m;
            v = ullmin2(v, k64);
        }
        for (int r = 0; r < KSEL; r++) {
            unsigned long long vv = v;
#pragma unroll
            for (int off = 16; off; off >>= 1)
                vv = ullmin2(vv, __shfl_down_sync(0xffffffffu, vv, off));
            if (lane == 0) s_wmin[sub][w] = vv;
            asm volatile("bar.sync %0, 128;" :: "r"(sub + 1));
            if (t == 0) {
                unsigned long long a0 = ullmin2(s_wmin[sub][0], s_wmin[sub][1]);
                unsigned long long a1 = ullmin2(s_wmin[sub][2], s_wmin[sub][3]);
                s_winner[sub] = ullmin2(a0, a1);
            }
            asm volatile("bar.sync %0, 128;" :: "r"(sub + 1));
            unsigned long long win = s_winner[sub];
            int m = (int)win & 0xFFF;
            if (t == 0 && r > 0) s_nbr[sub][r - 1] = m;
            if (t == (m & 127)) {                     // owner rescans
                removed |= 1u << (m >> 7);
                unsigned long long nb = ~0ull;
#pragma unroll 1
                for (int i = 0; i < 32; i++) {
                    if ((removed >> i) & 1u) continue;
                    int mm = t + 128 * i;
                    float4 p = g_pos4[browbase + mm];
                    float d2 = q.w + p.w -
                               2.f * (q.x * p.x + q.y * p.y + q.z * p.z);
                    unsigned long long k64 =
                        (((unsigned long long)fkey(d2)) << 13) | (unsigned int)mm;
                    nb = ullmin2(nb, k64);
                }
                v = nb;
            }
        }
    }
    __syncthreads();

    // ---- softmax over the 20 neighbors (warp 0 of each subgroup) ----
    if (t < 32) {
        float e = -1e30f;
        if (t < KSEL - 1) {
            int m = s_nbr[sub][t];
            float val = g_f1[row] + g_f2[browbase + m];
            e = val > 0.f ? val : 0.2f * val;          // leaky relu 0.2
        }
        float mx = e;
#pragma unroll
        for (int off = 16; off; off >>= 1)
            mx = fmaxf(mx, __shfl_xor_sync(0xffffffffu, mx, off));
        float ex = (t < KSEL - 1) ? expf(e - mx) : 0.f;
        float sm = ex;
#pragma unroll
        for (int off = 16; off; off >>= 1)
            sm += __shfl_xor_sync(0xffffffffu, sm, off);
        if (t < KSEL - 1) s_attn[sub][t] = ex / sm;
    }
    __syncthreads();

    // ---- weighted Wh gather + base + elu ----
    if (t < FDIM) {
        float acc = g_base[row * FDIM + t];
#pragma unroll
        for (int i = 0; i < KSEL - 1; i++) {
            int m = s_nbr[sub][i];
            acc += s_attn[sub][i] * g_Wh[(browbase + m) * FDIM + t];
        }
        float o = acc > 0.f ? acc : expm1f(acc);       // elu(alpha=1)
        out[row * FDIM + t] = o;
    }
}

// ---------------- launch ----------------------------------------------------
extern "C" void kernel_launch(void* const* d_in, const int* in_sizes, int n_in,
                              void* d_out, int out_size) {
    (void)in_sizes; (void)n_in; (void)out_size;
    const float* x   = (const float*)d_in[0];
    const float* pos = (const float*)d_in[1];
    const float* W   = (const float*)d_in[2];
    const float* a   = (const float*)d_in[3];
    const float* Wp  = (const float*)d_in[4];
    const float* bp  = (const float*)d_in[5];
    float* out = (float*)d_out;

    prep_kernel<<<NB, FDIM>>>(x, pos, W, a, Wp, bp);
    knn_attn_kernel<<<NB / QPB, TPB>>>(out);
}

// round 4
// speedup vs baseline: 1.1772x; 1.1355x over previous
#include <cuda_runtime.h>

#define NB    8192     // B*N total rows
#define NPTS  4096     // nodes per batch
#define FDIM  64
#define KSEL  21       // k+1 (drop the smallest afterwards)
#define QPB   4        // queries per block
#define TPB   512
#define CHUNK 1024     // pos4 staging chunk (float4 count)
#define LKEEP 4        // per-thread sorted list length (4th = bound)

// ---------------- scratch (device globals; no allocation allowed) ----------
__device__ float4 g_pos4[NB];          // (x,y,z,sq)
__device__ float  g_Wh[NB * FDIM];
__device__ float  g_f1[NB];
__device__ float  g_f2[NB];
__device__ float  g_base[NB * FDIM];   // relu(pos@Wp + bp)

// order-preserving float->uint transform (1 SHF + 1 LOP3)
__device__ __forceinline__ unsigned int fkey(float f) {
    unsigned int u = __float_as_uint(f);
    return u ^ (0x80000000u | (unsigned int)((int)u >> 31));
}
__device__ __forceinline__ unsigned long long ullmin2(unsigned long long a,
                                                      unsigned long long b) {
    return a < b ? a : b;
}

// ---------------- kernel A: per-node prep ----------------------------------
__global__ void prep_kernel(const float* __restrict__ x,
                            const float* __restrict__ pos,
                            const float* __restrict__ W,
                            const float* __restrict__ a,
                            const float* __restrict__ Wp,
                            const float* __restrict__ bp) {
    int row = blockIdx.x;        // 0..NB-1
    int j   = threadIdx.x;       // 0..63
    __shared__ float xs[FDIM];
    __shared__ float red[4];

    xs[j] = x[row * FDIM + j];
    __syncthreads();

    float acc = 0.f;
#pragma unroll 16
    for (int i = 0; i < FDIM; i++)
        acc += xs[i] * W[i * FDIM + j];
    g_Wh[row * FDIM + j] = acc;

    float p1 = acc * a[j];
    float p2 = acc * a[FDIM + j];
#pragma unroll
    for (int off = 16; off; off >>= 1) {
        p1 += __shfl_down_sync(0xffffffffu, p1, off);
        p2 += __shfl_down_sync(0xffffffffu, p2, off);
    }
    int lane = j & 31, wid = j >> 5;
    if (lane == 0) { red[wid] = p1; red[2 + wid] = p2; }

    float px = pos[row * 3 + 0];
    float py = pos[row * 3 + 1];
    float pz = pos[row * 3 + 2];
    float bj = px * Wp[j] + py * Wp[FDIM + j] + pz * Wp[2 * FDIM + j] + bp[j];
    g_base[row * FDIM + j] = bj > 0.f ? bj : 0.f;

    __syncthreads();
    if (j == 0) {
        g_f1[row] = red[0] + red[1];
        g_f2[row] = red[2] + red[3];
        float sq  = px * px + py * py + pz * pz;
        g_pos4[row] = make_float4(px, py, pz, sq);
    }
}

// branchless stable insert level: (ck,ci) bubbles down past (kk,ii)
#define INS_LEV(kk, ii)                                   \
    {                                                     \
        bool c = ck < kk;                                 \
        unsigned int tk = c ? kk : ck, ti = c ? ii : ci;  \
        kk = c ? ck : kk;  ii = c ? ci : ii;              \
        ck = tk;  ci = ti;                                \
    }

// ---------------- kernel B: kNN(21) + attention epilogue --------------------
__global__ void __launch_bounds__(TPB)
knn_attn_kernel(float* __restrict__ out) {
    __shared__ float4 s_chunk[CHUNK];                        // 16 KB
    __shared__ unsigned long long s_lists[QPB][128][LKEEP];  // 16 KB
    __shared__ float4 s_q[QPB];
    __shared__ int    s_nbr[QPB][KSEL - 1];
    __shared__ float  s_attn[QPB][KSEL - 1];
    __shared__ int    s_bad[QPB];
    __shared__ unsigned long long s_wmin[QPB][4];
    __shared__ unsigned long long s_winner[QPB];

    int tid = threadIdx.x;
    int sub = tid >> 7;          // query slot (0..3)
    int t   = tid & 127;         // thread within query group
    int qbase    = blockIdx.x * QPB;
    int browbase = (qbase >> 12) << 12;    // first row of this batch
    int row      = qbase + sub;

    if (tid < QPB) { s_q[tid] = g_pos4[qbase + tid]; s_bad[tid] = 0; }
    __syncthreads();
    float4 q = s_q[sub];

    // ---- phase 1: distances + branchless register top-4 (32-bit keys) ----
    unsigned int k0 = 0xFFFFFFFFu, k1 = 0xFFFFFFFFu,
                 k2 = 0xFFFFFFFFu, k3 = 0xFFFFFFFFu;
    unsigned int i0 = 0xFFFu, i1 = 0xFFFu, i2 = 0xFFFu, i3 = 0xFFFu;
#pragma unroll 1
    for (int c = 0; c < NPTS / CHUNK; c++) {
        s_chunk[tid]       = g_pos4[browbase + c * CHUNK + tid];
        s_chunk[tid + TPB] = g_pos4[browbase + c * CHUNK + tid + TPB];
        __syncthreads();
        int mb = c * CHUNK + t;
#pragma unroll
        for (int j = 0; j < CHUNK / 128; j++) {
            float4 p = s_chunk[t + 128 * j];
            float dot = q.x * p.x;
            dot = fmaf(q.y, p.y, dot);
            dot = fmaf(q.z, p.z, dot);
            float d2 = fmaf(-2.f, dot, q.w + p.w);
            unsigned int ck = fkey(d2);
            unsigned int ci = (unsigned int)(mb + 128 * j);
            INS_LEV(k0, i0)
            INS_LEV(k1, i1)
            INS_LEV(k2, i2)
            INS_LEV(k3, i3)
        }
        __syncthreads();
    }
    // pack: key<<13 | flag<<12 | idx ; flag marks the bound element (4th)
    s_lists[sub][t][0] = (((unsigned long long)k0) << 13) | i0;
    s_lists[sub][t][1] = (((unsigned long long)k1) << 13) | i1;
    s_lists[sub][t][2] = (((unsigned long long)k2) << 13) | i2;
    s_lists[sub][t][3] = (((unsigned long long)k3) << 13) | 0x1000ull | i3;
    __syncthreads();

    // ---- phase 2: 128-way merge, one warp per query ----
    if (t < 32) {
        int l = t;
        unsigned long long h[4];
        int hp[4];
#pragma unroll
        for (int s = 0; s < 4; s++) {
            h[s] = s_lists[sub][4 * l + s][0];
            hp[s] = 1;
        }
#pragma unroll 1
        for (int r = 0; r < KSEL; r++) {
            unsigned long long cur = ullmin2(ullmin2(h[0], h[1]),
                                             ullmin2(h[2], h[3]));
#pragma unroll
            for (int off = 16; off; off >>= 1)
                cur = ullmin2(cur, __shfl_xor_sync(0xffffffffu, cur, off));
            if ((cur >> 12) & 1ull) {
                if (l == 0) s_bad[sub] = 1;      // bound selected -> fallback
            }
            int m = (int)cur & 0xFFF;
            if (l == 0 && r > 0) s_nbr[sub][r - 1] = m;
#pragma unroll
            for (int s = 0; s < 4; s++) {
                if (h[s] == cur) {
                    h[s] = (hp[s] < LKEEP) ? s_lists[sub][4 * l + s][hp[s]]
                                           : ~0ull;
                    hp[s]++;
                }
            }
        }
    }
    __syncthreads();

    // ---- exact fallback (rare, ~0.3% of queries): full extract-min ----
    if (s_bad[sub]) {
        unsigned int removed = 0;
        int lane = t & 31, w = t >> 5;
        unsigned long long v = ~0ull;
#pragma unroll 1
        for (int i = 0; i < 32; i++) {
            int m = t + 128 * i;
            float4 p = g_pos4[browbase + m];
            float dot = q.x * p.x;
            dot = fmaf(q.y, p.y, dot);
            dot = fmaf(q.z, p.z, dot);
            float d2 = fmaf(-2.f, dot, q.w + p.w);
            unsigned long long k64 =
                (((unsigned long long)fkey(d2)) << 13) | (unsigned int)m;
            v = ullmin2(v, k64);
        }
        for (int r = 0; r < KSEL; r++) {
            unsigned long long vv = v;
#pragma unroll
            for (int off = 16; off; off >>= 1)
                vv = ullmin2(vv, __shfl_down_sync(0xffffffffu, vv, off));
            if (lane == 0) s_wmin[sub][w] = vv;
            asm volatile("bar.sync %0, 128;" :: "r"(sub + 1));
            if (t == 0) {
                unsigned long long a0 = ullmin2(s_wmin[sub][0], s_wmin[sub][1]);
                unsigned long long a1 = ullmin2(s_wmin[sub][2], s_wmin[sub][3]);
                s_winner[sub] = ullmin2(a0, a1);
            }
            asm volatile("bar.sync %0, 128;" :: "r"(sub + 1));
            unsigned long long win = s_winner[sub];
            int m = (int)win & 0xFFF;
            if (t == 0 && r > 0) s_nbr[sub][r - 1] = m;
            if (t == (m & 127)) {                     // owner rescans
                removed |= 1u << (m >> 7);
                unsigned long long nb = ~0ull;
#pragma unroll 1
                for (int i = 0; i < 32; i++) {
                    if ((removed >> i) & 1u) continue;
                    int mm = t + 128 * i;
                    float4 p = g_pos4[browbase + mm];
                    float dot = q.x * p.x;
                    dot = fmaf(q.y, p.y, dot);
                    dot = fmaf(q.z, p.z, dot);
                    float d2 = fmaf(-2.f, dot, q.w + p.w);
                    unsigned long long k64 =
                        (((unsigned long long)fkey(d2)) << 13) |
                        (unsigned int)mm;
                    nb = ullmin2(nb, k64);
                }
                v = nb;
            }
        }
    }
    __syncthreads();

    // ---- softmax over the 20 neighbors (warp 0 of each subgroup) ----
    if (t < 32) {
        float e = -1e30f;
        if (t < KSEL - 1) {
            int m = s_nbr[sub][t];
            float val = g_f1[row] + g_f2[browbase + m];
            e = val > 0.f ? val : 0.2f * val;          // leaky relu 0.2
        }
        float mx = e;
#pragma unroll
        for (int off = 16; off; off >>= 1)
            mx = fmaxf(mx, __shfl_xor_sync(0xffffffffu, mx, off));
        float ex = (t < KSEL - 1) ? expf(e - mx) : 0.f;
        float sm = ex;
#pragma unroll
        for (int off = 16; off; off >>= 1)
            sm += __shfl_xor_sync(0xffffffffu, sm, off);
        if (t < KSEL - 1) s_attn[sub][t] = ex / sm;
    }
    __syncthreads();

    // ---- weighted Wh gather + base + elu ----
    if (t < FDIM) {
        float acc = g_base[row * FDIM + t];
#pragma unroll
        for (int i = 0; i < KSEL - 1; i++) {
            int m = s_nbr[sub][i];
            acc += s_attn[sub][i] * g_Wh[(browbase + m) * FDIM + t];
        }
        float o = acc > 0.f ? acc : expm1f(acc);       // elu(alpha=1)
        out[row * FDIM + t] = o;
    }
}

// ---------------- launch ----------------------------------------------------
extern "C" void kernel_launch(void* const* d_in, const int* in_sizes, int n_in,
                              void* d_out, int out_size) {
    (void)in_sizes; (void)n_in; (void)out_size;
    const float* x   = (const float*)d_in[0];
    const float* pos = (const float*)d_in[1];
    const float* W   = (const float*)d_in[2];
    const float* a   = (const float*)d_in[3];
    const float* Wp  = (const float*)d_in[4];
    const float* bp  = (const float*)d_in[5];
    float* out = (float*)d_out;

    prep_kernel<<<NB, FDIM>>>(x, pos, W, a, Wp, bp);
    knn_attn_kernel<<<NB / QPB, TPB>>>(out);
}

// round 5
// speedup vs baseline: 1.3879x; 1.1790x over previous
#include <cuda_runtime.h>

#define NB    8192     // B*N total rows
#define NPTS  4096     // nodes per batch
#define FDIM  64
#define KSEL  21       // k+1 (drop the smallest afterwards)
#define QPB   4        // queries per block
#define TPB   512

// ---------------- scratch (device globals; no allocation allowed) ----------
__device__ float4 g_pos4[NB];          // (x,y,z,sq)
__device__ float  g_Wh[NB * FDIM];
__device__ float  g_f1[NB];
__device__ float  g_f2[NB];
__device__ float  g_base[NB * FDIM];   // relu(pos@Wp + bp)

__device__ __forceinline__ unsigned int fkey(float f) {
    unsigned int u = __float_as_uint(f);
    return u ^ (0x80000000u | (unsigned int)((int)u >> 31));
}
__device__ __forceinline__ unsigned long long ullmin2(unsigned long long a,
                                                      unsigned long long b) {
    return a < b ? a : b;
}

// ---------------- kernel A: per-node prep ----------------------------------
__global__ void prep_kernel(const float* __restrict__ x,
                            const float* __restrict__ pos,
                            const float* __restrict__ W,
                            const float* __restrict__ a,
                            const float* __restrict__ Wp,
                            const float* __restrict__ bp) {
    int row = blockIdx.x;
    int j   = threadIdx.x;
    __shared__ float xs[FDIM];
    __shared__ float red[4];

    xs[j] = x[row * FDIM + j];
    __syncthreads();

    float acc = 0.f;
#pragma unroll 16
    for (int i = 0; i < FDIM; i++)
        acc += xs[i] * W[i * FDIM + j];
    g_Wh[row * FDIM + j] = acc;

    float p1 = acc * a[j];
    float p2 = acc * a[FDIM + j];
#pragma unroll
    for (int off = 16; off; off >>= 1) {
        p1 += __shfl_down_sync(0xffffffffu, p1, off);
        p2 += __shfl_down_sync(0xffffffffu, p2, off);
    }
    int lane = j & 31, wid = j >> 5;
    if (lane == 0) { red[wid] = p1; red[2 + wid] = p2; }

    float px = pos[row * 3 + 0];
    float py = pos[row * 3 + 1];
    float pz = pos[row * 3 + 2];
    float bj = px * Wp[j] + py * Wp[FDIM + j] + pz * Wp[2 * FDIM + j] + bp[j];
    g_base[row * FDIM + j] = bj > 0.f ? bj : 0.f;

    __syncthreads();
    if (j == 0) {
        g_f1[row] = red[0] + red[1];
        g_f2[row] = red[2] + red[3];
        float sq  = px * px + py * py + pz * pz;
        g_pos4[row] = make_float4(px, py, pz, sq);
    }
}

// branchless stable insert level (swap form: no temporaries needed)
#define INS_LEV(kk, ii, ck, ci)                           \
    {                                                     \
        bool c = ck < kk;                                 \
        unsigned int nk = c ? ck : kk, ni = c ? ci : ii;  \
        ck = c ? kk : ck;  ci = c ? ii : ci;              \
        kk = nk;  ii = ni;                                \
    }

// compare-exchange on packed u64 (lo=min, hi=max)
#define CE64(lo, hi)                                      \
    {                                                     \
        unsigned long long mn = lo < hi ? lo : hi;        \
        hi = lo < hi ? hi : lo;                           \
        lo = mn;                                          \
    }

// ---------------- kernel B: kNN(21) + attention epilogue --------------------
// Block = 4 queries, 128 threads/query. Each thread scans its 32 candidates
// as TWO independent cascade streams (ILP), direct LDG from L2, no barriers.
// One warp per query merges the 128 sorted 4-lists with REDUX.MIN rounds.
__global__ void __launch_bounds__(TPB, 2)
knn_attn_kernel(float* __restrict__ out) {
    __shared__ unsigned long long s_lists[QPB][128][4];     // 16 KB
    __shared__ float4 s_q[QPB];
    __shared__ int    s_nbr[QPB][KSEL - 1];
    __shared__ float  s_attn[QPB][KSEL - 1];
    __shared__ int    s_bad[QPB];
    __shared__ unsigned long long s_wmin[QPB][4];
    __shared__ unsigned long long s_winner[QPB];

    int tid = threadIdx.x;
    int sub = tid >> 7;          // query slot (0..3)
    int t   = tid & 127;         // thread within query group
    int qbase    = blockIdx.x * QPB;
    int browbase = (qbase >> 12) << 12;    // first row of this batch
    int row      = qbase + sub;

    if (tid < QPB) { s_q[tid] = g_pos4[qbase + tid]; s_bad[tid] = 0; }
    __syncthreads();
    float4 q = s_q[sub];
    const float4* pb = g_pos4 + browbase;

    // ---- phase 1: two independent branchless top-4 cascades ----
    unsigned int ak0 = ~0u, ak1 = ~0u, ak2 = ~0u, ak3 = ~0u;
    unsigned int ai0 = 0xFFFu, ai1 = 0xFFFu, ai2 = 0xFFFu, ai3 = 0xFFFu;
    unsigned int bk0 = ~0u, bk1 = ~0u, bk2 = ~0u, bk3 = ~0u;
    unsigned int bi0 = 0xFFFu, bi1 = 0xFFFu, bi2 = 0xFFFu, bi3 = 0xFFFu;
#pragma unroll 4
    for (int i = 0; i < 16; i++) {
        int mA = t + 128 * i;
        int mB = t + 128 * (i + 16);
        float4 pA = pb[mA];
        float4 pB = pb[mB];

        float dotA = fmaf(q.z, pA.z, fmaf(q.y, pA.y, q.x * pA.x));
        float d2A  = fmaf(-2.f, dotA, q.w + pA.w);
        unsigned int ck = fkey(d2A), ci = (unsigned int)mA;
        INS_LEV(ak0, ai0, ck, ci)
        INS_LEV(ak1, ai1, ck, ci)
        INS_LEV(ak2, ai2, ck, ci)
        INS_LEV(ak3, ai3, ck, ci)

        float dotB = fmaf(q.z, pB.z, fmaf(q.y, pB.y, q.x * pB.x));
        float d2B  = fmaf(-2.f, dotB, q.w + pB.w);
        unsigned int dk = fkey(d2B), di = (unsigned int)mB;
        INS_LEV(bk0, bi0, dk, di)
        INS_LEV(bk1, bi1, dk, di)
        INS_LEV(bk2, bi2, dk, di)
        INS_LEV(bk3, bi3, dk, di)
    }

    // ---- union-merge the two sorted 4-lists (bitonic half-clean + sort) ----
    {
        unsigned long long pa0 = (((unsigned long long)ak0) << 13) | ai0;
        unsigned long long pa1 = (((unsigned long long)ak1) << 13) | ai1;
        unsigned long long pa2 = (((unsigned long long)ak2) << 13) | ai2;
        unsigned long long pa3 = (((unsigned long long)ak3) << 13) | ai3;
        unsigned long long pb0 = (((unsigned long long)bk0) << 13) | bi0;
        unsigned long long pb1 = (((unsigned long long)bk1) << 13) | bi1;
        unsigned long long pb2 = (((unsigned long long)bk2) << 13) | bi2;
        unsigned long long pb3 = (((unsigned long long)bk3) << 13) | bi3;
        unsigned long long c0 = ullmin2(pa0, pb3);
        unsigned long long c1 = ullmin2(pa1, pb2);
        unsigned long long c2 = ullmin2(pa2, pb1);
        unsigned long long c3 = ullmin2(pa3, pb0);
        CE64(c0, c2) CE64(c1, c3) CE64(c0, c1) CE64(c2, c3)
        s_lists[sub][t][0] = c0;
        s_lists[sub][t][1] = c1;
        s_lists[sub][t][2] = c2;
        s_lists[sub][t][3] = c3 | 0x1000ull;   // flag bound (4th)
    }
    __syncthreads();

    // ---- phase 2: 128-way merge, one warp per query, REDUX rounds ----
    if (t < 32) {
        int l = t;
        unsigned int hk[4], hi[4], hf[4];
        int hp[4];
#pragma unroll
        for (int s = 0; s < 4; s++) {
            unsigned long long v = s_lists[sub][4 * l + s][0];
            hk[s] = (unsigned int)(v >> 13);
            hi[s] = (unsigned int)v & 0xFFFu;
            hf[s] = (unsigned int)(v >> 12) & 1u;
            hp[s] = 1;
        }
#pragma unroll 1
        for (int r = 0; r < KSEL; r++) {
            unsigned int cur = min(min(hk[0], hk[1]), min(hk[2], hk[3]));
            unsigned int w = __reduce_min_sync(0xffffffffu, cur);
            unsigned int cim = 0xFFFFu;
#pragma unroll
            for (int s = 0; s < 4; s++)
                cim = (hk[s] == w) ? min(cim, hi[s]) : cim;
            unsigned int m = __reduce_min_sync(0xffffffffu, cim);
            if (l == 0 && r > 0) s_nbr[sub][r - 1] = (int)m;
#pragma unroll
            for (int s = 0; s < 4; s++) {
                if (hk[s] == w && hi[s] == m) {
                    if (hf[s]) s_bad[sub] = 1;        // bound hit -> fallback
                    unsigned long long v =
                        (hp[s] < 4) ? s_lists[sub][4 * l + s][hp[s]] : ~0ull;
                    hk[s] = (unsigned int)(v >> 13);
                    hi[s] = (unsigned int)v & 0xFFFu;
                    hf[s] = (unsigned int)(v >> 12) & 1u;
                    hp[s]++;
                }
            }
        }
    }
    __syncthreads();

    // ---- exact fallback (rare): full extract-min with named barriers ----
    if (s_bad[sub]) {
        unsigned int removed = 0;
        int lane = t & 31, w = t >> 5;
        unsigned long long v = ~0ull;
#pragma unroll 1
        for (int i = 0; i < 32; i++) {
            int m = t + 128 * i;
            float4 p = pb[m];
            float dot = fmaf(q.z, p.z, fmaf(q.y, p.y, q.x * p.x));
            float d2  = fmaf(-2.f, dot, q.w + p.w);
            unsigned long long k64 =
                (((unsigned long long)fkey(d2)) << 13) | (unsigned int)m;
            v = ullmin2(v, k64);
        }
        for (int r = 0; r < KSEL; r++) {
            unsigned long long vv = v;
#pragma unroll
            for (int off = 16; off; off >>= 1)
                vv = ullmin2(vv, __shfl_down_sync(0xffffffffu, vv, off));
            if (lane == 0) s_wmin[sub][w] = vv;
            asm volatile("bar.sync %0, 128;" :: "r"(sub + 1));
            if (t == 0) {
                unsigned long long a0 = ullmin2(s_wmin[sub][0], s_wmin[sub][1]);
                unsigned long long a1 = ullmin2(s_wmin[sub][2], s_wmin[sub][3]);
                s_winner[sub] = ullmin2(a0, a1);
            }
            asm volatile("bar.sync %0, 128;" :: "r"(sub + 1));
            unsigned long long win = s_winner[sub];
            int m = (int)win & 0xFFF;
            if (t == 0 && r > 0) s_nbr[sub][r - 1] = m;
            if (t == (m & 127)) {
                removed |= 1u << (m >> 7);
                unsigned long long nb = ~0ull;
#pragma unroll 1
                for (int i = 0; i < 32; i++) {
                    if ((removed >> i) & 1u) continue;
                    int mm = t + 128 * i;
                    float4 p = pb[mm];
                    float dot = fmaf(q.z, p.z, fmaf(q.y, p.y, q.x * p.x));
                    float d2  = fmaf(-2.f, dot, q.w + p.w);
                    unsigned long long k64 =
                        (((unsigned long long)fkey(d2)) << 13) |
                        (unsigned int)mm;
                    nb = ullmin2(nb, k64);
                }
                v = nb;
            }
        }
    }
    __syncthreads();

    // ---- softmax over the 20 neighbors (warp 0 of each subgroup) ----
    if (t < 32) {
        float e = -1e30f;
        if (t < KSEL - 1) {
            int m = s_nbr[sub][t];
            float val = g_f1[row] + g_f2[browbase + m];
            e = val > 0.f ? val : 0.2f * val;          // leaky relu 0.2
        }
        float mx = e;
#pragma unroll
        for (int off = 16; off; off >>= 1)
            mx = fmaxf(mx, __shfl_xor_sync(0xffffffffu, mx, off));
        float ex = (t < KSEL - 1) ? expf(e - mx) : 0.f;
        float sm = ex;
#pragma unroll
        for (int off = 16; off; off >>= 1)
            sm += __shfl_xor_sync(0xffffffffu, sm, off);
        if (t < KSEL - 1) s_attn[sub][t] = ex / sm;
    }
    __syncthreads();

    // ---- weighted Wh gather + base + elu ----
    if (t < FDIM) {
        float acc = g_base[row * FDIM + t];
#pragma unroll
        for (int i = 0; i < KSEL - 1; i++) {
            int m = s_nbr[sub][i];
            acc += s_attn[sub][i] * g_Wh[(browbase + m) * FDIM + t];
        }
        float o = acc > 0.f ? acc : expm1f(acc);       // elu(alpha=1)
        out[row * FDIM + t] = o;
    }
}

// ---------------- launch ----------------------------------------------------
extern "C" void kernel_launch(void* const* d_in, const int* in_sizes, int n_in,
                              void* d_out, int out_size) {
    (void)in_sizes; (void)n_in; (void)out_size;
    const float* x   = (const float*)d_in[0];
    const float* pos = (const float*)d_in[1];
    const float* W   = (const float*)d_in[2];
    const float* a   = (const float*)d_in[3];
    const float* Wp  = (const float*)d_in[4];
    const float* bp  = (const float*)d_in[5];
    float* out = (float*)d_out;

    prep_kernel<<<NB, FDIM>>>(x, pos, W, a, Wp, bp);
    knn_attn_kernel<<<NB / QPB, TPB>>>(out);
}